// round 10
// baseline (speedup 1.0000x reference)
#include <cuda_runtime.h>
#include <cstdint>

#define N_NODES 100000
#define N_EDGES 3200000
#define N_GRAPHS 512
#define IN_CH 50
#define HID 256
#define KDIM 100            // concatenated feature dim: [x(50) | agg(50)]
#define AGG_STR 52          // padded g_agg row stride (floats): 208 B, 16B-aligned
#define TILE_N 64           // nodes per block in fused GEMM
#define KC 25               // k-rows per smem chunk
#define NCHUNK 4            // KDIM / KC
#define FS_STRIDE 68        // padded Fs row (floats), 17 float4

// ---------------- device scratch ----------------
__device__ __align__(16) float g_agg[N_NODES * AGG_STR];   // padded neighbor sums
__device__ __align__(16) float g_cnt[N_NODES];             // edges per dst node
__device__ __align__(16) float g_pooled[N_GRAPHS * HID];   // per-graph h sums
__device__ __align__(16) float g_gcnt[N_GRAPHS];           // nodes per graph

// ---------------- packed f32x2 helpers (sm_100+) ----------------
__device__ __forceinline__ unsigned long long pack2(float lo, float hi) {
    unsigned long long r;
    asm("mov.b64 %0, {%1, %2};" : "=l"(r) : "f"(lo), "f"(hi));
    return r;
}
__device__ __forceinline__ void unpack2(unsigned long long v, float& lo, float& hi) {
    asm("mov.b64 {%0, %1}, %2;" : "=f"(lo), "=f"(hi) : "l"(v));
}
__device__ __forceinline__ void ffma2(unsigned long long& d,
                                      unsigned long long a, unsigned long long b) {
    asm("fma.rn.f32x2 %0, %1, %2, %0;" : "+l"(d) : "l"(a), "l"(b));
}

// ---------------- kernel 0: zero scratch ----------------
__global__ __launch_bounds__(256) void zero_scratch()
{
    int i = blockIdx.x * blockDim.x + threadIdx.x;
    int stride = gridDim.x * blockDim.x;
    for (; i < N_NODES * AGG_STR / 4; i += stride)
        ((float4*)g_agg)[i] = make_float4(0.f, 0.f, 0.f, 0.f);
    for (i = blockIdx.x * blockDim.x + threadIdx.x; i < N_NODES; i += stride)
        g_cnt[i] = 0.f;
    for (i = blockIdx.x * blockDim.x + threadIdx.x; i < N_GRAPHS * HID; i += stride)
        g_pooled[i] = 0.f;
    for (i = blockIdx.x * blockDim.x + threadIdx.x; i < N_GRAPHS; i += stride)
        g_gcnt[i] = 0.f;
}

// ---------------- kernel 1: edge scatter-mean (sum + count) ----------------
// One warp owns 32 consecutive edges. Coalesced int32 index loads, shfl
// broadcast. Lanes 0..12 each move one float4 (REDG.128, 52-float padded
// rows), lane 13 bumps the per-dst count. Lane 12's upper half is zero
// (channels 50,51 are padding; avoids OOB read on the last x row).
__global__ __launch_bounds__(256) void edge_scatter(
    const int* __restrict__ ei, const float* __restrict__ x)
{
    int warp = (blockIdx.x * blockDim.x + threadIdx.x) >> 5;
    int lane = threadIdx.x & 31;
    int e = warp * 32 + lane;
    int s = ei[e];
    int d = ei[N_EDGES + e];
    const float2* x2 = (const float2*)x;
    #pragma unroll 4
    for (int i = 0; i < 32; i++) {
        int si = __shfl_sync(0xffffffffu, s, i);
        int di = __shfl_sync(0xffffffffu, d, i);
        if (lane < 13) {
            float2 va = x2[si * 25 + lane * 2];
            float2 vb = make_float2(0.f, 0.f);
            if (lane < 12) vb = x2[si * 25 + lane * 2 + 1];
            float4 v = make_float4(va.x, va.y, vb.x, vb.y);
            atomicAdd((float4*)&g_agg[di * AGG_STR + lane * 4], v);
        } else if (lane == 13) {
            atomicAdd(&g_cnt[di], 1.0f);
        }
    }
}

// ---------------- kernel 2: nodes per graph (atomic-free) ------------------
__global__ __launch_bounds__(256) void count_nodes(const int* __restrict__ batch)
{
    int i = blockIdx.x * blockDim.x + threadIdx.x;
    if (i >= N_NODES) return;
    int g = batch[i];
    if (i == 0 || batch[i - 1] != g) {
        int j = i + 1;
        while (j < N_NODES && batch[j] == g) j++;
        g_gcnt[g] = (float)(j - i);
    }
}

// ---------------- kernel 3: fused node GEMM + leakyReLU + pool-scatter -----
// 512 threads, 64 nodes x 256 channels per block. Thread = 4 ch x 8 nodes,
// node pairs packed as f32x2 straight from LDS.128 (no pack MOVs on f).
// Inner loop per k: 3 LDS.128 + 4 MOV + 16 FFMA2.
__global__ __launch_bounds__(512, 2) void node_fused(
    const float* __restrict__ x,
    const int* __restrict__ batch,
    const float* __restrict__ W_l, const float* __restrict__ b_l,
    const float* __restrict__ W_r)
{
    __shared__ float sW[KC * HID];          // 25600 B
    __shared__ float sF[KC * FS_STRIDE];    // 6800 B
    __shared__ float sInv[TILE_N];
    __shared__ int   sGid[TILE_N];

    int tid = threadIdx.x;
    int n0  = blockIdx.x * TILE_N;

    if (tid < TILE_N) {
        int node = n0 + tid;
        float c = 1.0f; int g = -1;
        if (node < N_NODES) { c = g_cnt[node]; g = batch[node]; }
        sInv[tid] = 1.0f / fmaxf(c, 1.0f);
        sGid[tid] = g;
    }

    int tc = tid & 63;   // channel quad: channels tc*4 .. tc*4+3
    int tn = tid >> 6;   // node octet:   nodes tn*8 .. tn*8+7

    // acc[a][p]: a = channel (tc*4+a), p = node pair (2p, 2p+1) as f32x2
    unsigned long long acc[4][4];
    #pragma unroll
    for (int a = 0; a < 4; a++)
        #pragma unroll
        for (int p = 0; p < 4; p++) acc[a][p] = 0ull;

    const float4* sW4 = (const float4*)sW;          // row = 64 float4
    const ulonglong2* sFu = (const ulonglong2*)sF;  // row = 17 ulonglong2

    for (int kc = 0; kc < NCHUNK; kc++) {
        __syncthreads();
        // stage weights chunk: sW[kk][c], global k = kc*25+kk
        for (int idx = tid; idx < KC * HID; idx += 512) {
            int c  = idx / KC;
            int kk = idx - c * KC;
            int k  = kc * KC + kk;
            float v = (k < IN_CH) ? W_r[c * IN_CH + k]
                                  : W_l[c * IN_CH + k - IN_CH];
            sW[kk * HID + c] = v;
        }
        // stage feature chunk: sF[kk][n]
        for (int idx = tid; idx < KC * TILE_N; idx += 512) {
            int n  = idx / KC;
            int kk = idx - n * KC;
            int k  = kc * KC + kk;
            int node = n0 + n;
            float v = 0.0f;
            if (node < N_NODES) {
                v = (k < IN_CH) ? x[node * IN_CH + k]
                                : g_agg[node * AGG_STR + k - IN_CH] * sInv[n];
            }
            sF[kk * FS_STRIDE + n] = v;
        }
        __syncthreads();

        #pragma unroll
        for (int kk = 0; kk < KC; kk++) {
            float4 w = sW4[kk * 64 + tc];                 // 4 channels
            ulonglong2 fA = sFu[kk * 17 + tn * 2];        // node pairs 0,1
            ulonglong2 fB = sFu[kk * 17 + tn * 2 + 1];    // node pairs 2,3
            unsigned long long wb[4];
            wb[0] = pack2(w.x, w.x);
            wb[1] = pack2(w.y, w.y);
            wb[2] = pack2(w.z, w.z);
            wb[3] = pack2(w.w, w.w);
            unsigned long long fp[4] = {fA.x, fA.y, fB.x, fB.y};
            #pragma unroll
            for (int a = 0; a < 4; a++)
                #pragma unroll
                for (int p = 0; p < 4; p++)
                    ffma2(acc[a][p], wb[a], fp[p]);
        }
    }

    // epilogue: unpack, bias + leakyReLU, run-merged scalar REDs (batch sorted)
    float h[4][8];
    #pragma unroll
    for (int a = 0; a < 4; a++)
        #pragma unroll
        for (int p = 0; p < 4; p++)
            unpack2(acc[a][p], h[a][2 * p], h[a][2 * p + 1]);

    float4 bq = ((const float4*)b_l)[tc];
    float bias[4] = {bq.x, bq.y, bq.z, bq.w};

    float run[4];
    #pragma unroll
    for (int a = 0; a < 4; a++) run[a] = 0.0f;
    int runG = sGid[tn * 8];

    #pragma unroll
    for (int j = 0; j < 8; j++) {
        int g = sGid[tn * 8 + j];
        if (g != runG) {
            if (runG >= 0) {
                #pragma unroll
                for (int a = 0; a < 4; a++)
                    atomicAdd(&g_pooled[runG * HID + tc * 4 + a], run[a]);
            }
            #pragma unroll
            for (int a = 0; a < 4; a++) run[a] = 0.0f;
            runG = g;
        }
        if (g >= 0) {
            #pragma unroll
            for (int a = 0; a < 4; a++) {
                float v = h[a][j] + bias[a];
                v = v > 0.f ? v : 0.01f * v;
                run[a] += v;
            }
        }
    }
    if (runG >= 0) {
        #pragma unroll
        for (int a = 0; a < 4; a++)
            atomicAdd(&g_pooled[runG * HID + tc * 4 + a], run[a]);
    }
}

// ---------------- kernel 4: pooled mean + classifier ----------------
__global__ __launch_bounds__(256) void finalize(
    const float* __restrict__ W_c, const float* __restrict__ b_c,
    float* __restrict__ out)
{
    int g = blockIdx.x;
    int t = threadIdx.x;
    float inv = 1.0f / fmaxf(g_gcnt[g], 1.0f);
    float p = g_pooled[g * HID + t] * inv;
    float s0 = p * W_c[t];
    float s1 = p * W_c[HID + t];
    #pragma unroll
    for (int off = 16; off > 0; off >>= 1) {
        s0 += __shfl_down_sync(0xffffffffu, s0, off);
        s1 += __shfl_down_sync(0xffffffffu, s1, off);
    }
    __shared__ float sh0[8], sh1[8];
    int lane = t & 31, wid = t >> 5;
    if (lane == 0) { sh0[wid] = s0; sh1[wid] = s1; }
    __syncthreads();
    if (t == 0) {
        float t0 = b_c[0], t1 = b_c[1];
        #pragma unroll
        for (int w = 0; w < 8; w++) { t0 += sh0[w]; t1 += sh1[w]; }
        out[g * 2 + 0] = t0;
        out[g * 2 + 1] = t1;
    }
}

// ---------------- launch: kernel launches ONLY ----------------
extern "C" void kernel_launch(void* const* d_in, const int* in_sizes, int n_in,
                              void* d_out, int out_size)
{
    const float* x     = (const float*)d_in[0];
    const int*   ei    = (const int*)d_in[1];    // int32 (JAX x64 disabled)
    const int*   batch = (const int*)d_in[2];    // int32
    const float* W_l   = (const float*)d_in[3];
    const float* b_l   = (const float*)d_in[4];
    const float* W_r   = (const float*)d_in[5];
    const float* W_c   = (const float*)d_in[6];
    const float* b_c   = (const float*)d_in[7];
    float*       out   = (float*)d_out;

    zero_scratch<<<592, 256>>>();
    edge_scatter<<<12500, 256>>>(ei, x);
    count_nodes<<<(N_NODES + 255) / 256, 256>>>(batch);
    node_fused<<<(N_NODES + TILE_N - 1) / TILE_N, 512>>>(x, batch, W_l, b_l, W_r);
    finalize<<<N_GRAPHS, 256>>>(W_c, b_c, out);
}

// round 11
// speedup vs baseline: 1.0751x; 1.0751x over previous
#include <cuda_runtime.h>
#include <cstdint>

#define N_NODES 100000
#define N_EDGES 3200000
#define N_GRAPHS 512
#define IN_CH 50
#define HID 256
#define KDIM 100            // concatenated feature dim: [x(50) | agg(50)]
#define TILE_N 128          // nodes per block in fused GEMM
#define KC 25               // k-rows per smem chunk
#define NCHUNK 4            // KDIM / KC
#define FS_STRIDE 136       // padded Fs row (floats): 34 x 16B, conflict-safe

// ---------------- device scratch ----------------
__device__ __align__(16) float g_agg[N_NODES * IN_CH];     // 20 MB neighbor sums
__device__ __align__(16) float g_cnt[N_NODES];             // edges per dst node
__device__ __align__(16) float g_pooled[N_GRAPHS * HID];   // per-graph h sums
__device__ __align__(16) float g_gcnt[N_GRAPHS];           // nodes per graph

// ---------------- packed f32x2 helpers (sm_100+) ----------------
__device__ __forceinline__ unsigned long long pack2(float lo, float hi) {
    unsigned long long r;
    asm("mov.b64 %0, {%1, %2};" : "=l"(r) : "f"(lo), "f"(hi));
    return r;
}
__device__ __forceinline__ void unpack2(unsigned long long v, float& lo, float& hi) {
    asm("mov.b64 {%0, %1}, %2;" : "=f"(lo), "=f"(hi) : "l"(v));
}
__device__ __forceinline__ void ffma2(unsigned long long& d,
                                      unsigned long long a, unsigned long long b) {
    asm("fma.rn.f32x2 %0, %1, %2, %0;" : "+l"(d) : "l"(a), "l"(b));
}

// ---------------- kernel 0: zero scratch ----------------
__global__ __launch_bounds__(256) void zero_scratch()
{
    int i = blockIdx.x * blockDim.x + threadIdx.x;
    int stride = gridDim.x * blockDim.x;
    for (; i < N_NODES * IN_CH / 4; i += stride)
        ((float4*)g_agg)[i] = make_float4(0.f, 0.f, 0.f, 0.f);
    for (i = blockIdx.x * blockDim.x + threadIdx.x; i < N_NODES; i += stride)
        g_cnt[i] = 0.f;
    for (i = blockIdx.x * blockDim.x + threadIdx.x; i < N_GRAPHS * HID; i += stride)
        g_pooled[i] = 0.f;
    for (i = blockIdx.x * blockDim.x + threadIdx.x; i < N_GRAPHS; i += stride)
        g_gcnt[i] = 0.f;
}

// ---------------- kernel 1: edge scatter-mean (R7-measured-best) -----------
// One warp owns 32 consecutive edges. Coalesced int32 index loads, shfl
// broadcast; lanes 0..24 each move one float2 (REDG.64), lane 25 counts.
__global__ __launch_bounds__(256) void edge_scatter(
    const int* __restrict__ ei, const float* __restrict__ x)
{
    int warp = (blockIdx.x * blockDim.x + threadIdx.x) >> 5;
    int lane = threadIdx.x & 31;
    int e = warp * 32 + lane;
    int s = ei[e];
    int d = ei[N_EDGES + e];
    const float2* x2 = (const float2*)x;
    #pragma unroll 4
    for (int i = 0; i < 32; i++) {
        int si = __shfl_sync(0xffffffffu, s, i);
        int di = __shfl_sync(0xffffffffu, d, i);
        if (lane < 25) {
            float2 v = x2[si * 25 + lane];
            atomicAdd((float2*)&g_agg[di * IN_CH + lane * 2], v);
        } else if (lane == 25) {
            atomicAdd(&g_cnt[di], 1.0f);
        }
    }
}

// ---------------- kernel 2: nodes per graph (atomic-free) ------------------
__global__ __launch_bounds__(256) void count_nodes(const int* __restrict__ batch)
{
    int i = blockIdx.x * blockDim.x + threadIdx.x;
    if (i >= N_NODES) return;
    int g = batch[i];
    if (i == 0 || batch[i - 1] != g) {
        int j = i + 1;
        while (j < N_NODES && batch[j] == g) j++;
        g_gcnt[g] = (float)(j - i);
    }
}

// ---------------- kernel 3: fused node GEMM + leakyReLU + pool-scatter -----
// 512 threads, 128 nodes x 256 channels per block. Thread = 4 ch x 16 nodes,
// node pairs as f32x2 straight from LDS.128. Per warp per k: 1 distinct
// LDS.128 (w) + 4 broadcast LDS.128 (f) = 8 wavefronts for 32 FFMA2.
__global__ __launch_bounds__(512, 1) void node_fused(
    const float* __restrict__ x,
    const int* __restrict__ batch,
    const float* __restrict__ W_l, const float* __restrict__ b_l,
    const float* __restrict__ W_r)
{
    __shared__ float sW[KC * HID];          // 25600 B
    __shared__ float sF[KC * FS_STRIDE];    // 13600 B
    __shared__ float sInv[TILE_N];
    __shared__ int   sGid[TILE_N];

    int tid = threadIdx.x;
    int n0  = blockIdx.x * TILE_N;

    if (tid < TILE_N) {
        int node = n0 + tid;
        float c = 1.0f; int g = -1;
        if (node < N_NODES) { c = g_cnt[node]; g = batch[node]; }
        sInv[tid] = 1.0f / fmaxf(c, 1.0f);
        sGid[tid] = g;
    }

    int tc = tid & 63;   // channel quad: channels tc*4 .. tc*4+3
    int tn = tid >> 6;   // node 16-group: nodes tn*16 .. tn*16+15

    // acc[a][p]: a = channel (tc*4+a), p = node pair (2p,2p+1) as f32x2
    unsigned long long acc[4][8];
    #pragma unroll
    for (int a = 0; a < 4; a++)
        #pragma unroll
        for (int p = 0; p < 8; p++) acc[a][p] = 0ull;

    const float4* sW4 = (const float4*)sW;          // row = 64 float4
    const ulonglong2* sFu = (const ulonglong2*)sF;  // row = 34 ulonglong2

    for (int kc = 0; kc < NCHUNK; kc++) {
        __syncthreads();
        // stage weights chunk: sW[kk][c], global k = kc*25+kk
        for (int idx = tid; idx < KC * HID; idx += 512) {
            int c  = idx / KC;
            int kk = idx - c * KC;
            int k  = kc * KC + kk;
            float v = (k < IN_CH) ? W_r[c * IN_CH + k]
                                  : W_l[c * IN_CH + k - IN_CH];
            sW[kk * HID + c] = v;
        }
        // stage feature chunk: sF[kk][n]
        for (int idx = tid; idx < KC * TILE_N; idx += 512) {
            int n  = idx / KC;
            int kk = idx - n * KC;
            int k  = kc * KC + kk;
            int node = n0 + n;
            float v = 0.0f;
            if (node < N_NODES) {
                v = (k < IN_CH) ? x[node * IN_CH + k]
                                : g_agg[node * IN_CH + k - IN_CH] * sInv[n];
            }
            sF[kk * FS_STRIDE + n] = v;
        }
        __syncthreads();

        #pragma unroll
        for (int kk = 0; kk < KC; kk++) {
            float4 w = sW4[kk * 64 + tc];                  // 4 channels
            ulonglong2 f0 = sFu[kk * 34 + tn * 4];         // node pairs 0,1
            ulonglong2 f1 = sFu[kk * 34 + tn * 4 + 1];     // node pairs 2,3
            ulonglong2 f2 = sFu[kk * 34 + tn * 4 + 2];     // node pairs 4,5
            ulonglong2 f3 = sFu[kk * 34 + tn * 4 + 3];     // node pairs 6,7
            unsigned long long wb[4];
            wb[0] = pack2(w.x, w.x);
            wb[1] = pack2(w.y, w.y);
            wb[2] = pack2(w.z, w.z);
            wb[3] = pack2(w.w, w.w);
            unsigned long long fp[8] = {f0.x, f0.y, f1.x, f1.y,
                                        f2.x, f2.y, f3.x, f3.y};
            #pragma unroll
            for (int a = 0; a < 4; a++)
                #pragma unroll
                for (int p = 0; p < 8; p++)
                    ffma2(acc[a][p], wb[a], fp[p]);
        }
    }

    // epilogue: unpack, bias + leakyReLU, run-merged scalar REDs (batch sorted)
    float4 bq = ((const float4*)b_l)[tc];
    float bias[4] = {bq.x, bq.y, bq.z, bq.w};

    float run[4];
    #pragma unroll
    for (int a = 0; a < 4; a++) run[a] = 0.0f;
    int runG = sGid[tn * 16];

    #pragma unroll
    for (int p = 0; p < 8; p++) {
        float hv[4][2];
        #pragma unroll
        for (int a = 0; a < 4; a++)
            unpack2(acc[a][p], hv[a][0], hv[a][1]);
        #pragma unroll
        for (int half = 0; half < 2; half++) {
            int g = sGid[tn * 16 + 2 * p + half];
            if (g != runG) {
                if (runG >= 0) {
                    #pragma unroll
                    for (int a = 0; a < 4; a++)
                        atomicAdd(&g_pooled[runG * HID + tc * 4 + a], run[a]);
                }
                #pragma unroll
                for (int a = 0; a < 4; a++) run[a] = 0.0f;
                runG = g;
            }
            if (g >= 0) {
                #pragma unroll
                for (int a = 0; a < 4; a++) {
                    float v = hv[a][half] + bias[a];
                    v = v > 0.f ? v : 0.01f * v;
                    run[a] += v;
                }
            }
        }
    }
    if (runG >= 0) {
        #pragma unroll
        for (int a = 0; a < 4; a++)
            atomicAdd(&g_pooled[runG * HID + tc * 4 + a], run[a]);
    }
}

// ---------------- kernel 4: pooled mean + classifier ----------------
__global__ __launch_bounds__(256) void finalize(
    const float* __restrict__ W_c, const float* __restrict__ b_c,
    float* __restrict__ out)
{
    int g = blockIdx.x;
    int t = threadIdx.x;
    float inv = 1.0f / fmaxf(g_gcnt[g], 1.0f);
    float p = g_pooled[g * HID + t] * inv;
    float s0 = p * W_c[t];
    float s1 = p * W_c[HID + t];
    #pragma unroll
    for (int off = 16; off > 0; off >>= 1) {
        s0 += __shfl_down_sync(0xffffffffu, s0, off);
        s1 += __shfl_down_sync(0xffffffffu, s1, off);
    }
    __shared__ float sh0[8], sh1[8];
    int lane = t & 31, wid = t >> 5;
    if (lane == 0) { sh0[wid] = s0; sh1[wid] = s1; }
    __syncthreads();
    if (t == 0) {
        float t0 = b_c[0], t1 = b_c[1];
        #pragma unroll
        for (int w = 0; w < 8; w++) { t0 += sh0[w]; t1 += sh1[w]; }
        out[g * 2 + 0] = t0;
        out[g * 2 + 1] = t1;
    }
}

// ---------------- launch: kernel launches ONLY ----------------
extern "C" void kernel_launch(void* const* d_in, const int* in_sizes, int n_in,
                              void* d_out, int out_size)
{
    const float* x     = (const float*)d_in[0];
    const int*   ei    = (const int*)d_in[1];    // int32 (JAX x64 disabled)
    const int*   batch = (const int*)d_in[2];    // int32
    const float* W_l   = (const float*)d_in[3];
    const float* b_l   = (const float*)d_in[4];
    const float* W_r   = (const float*)d_in[5];
    const float* W_c   = (const float*)d_in[6];
    const float* b_c   = (const float*)d_in[7];
    float*       out   = (float*)d_out;

    zero_scratch<<<592, 256>>>();
    edge_scatter<<<12500, 256>>>(ei, x);
    count_nodes<<<(N_NODES + 255) / 256, 256>>>(batch);
    node_fused<<<(N_NODES + TILE_N - 1) / TILE_N, 512>>>(x, batch, W_l, b_l, W_r);
    finalize<<<N_GRAPHS, 256>>>(W_c, b_c, out);
}

// round 12
// speedup vs baseline: 1.3180x; 1.2260x over previous
#include <cuda_runtime.h>
#include <cstdint>

#define N_NODES 100000
#define N_EDGES 3200000
#define N_GRAPHS 512
#define IN_CH 50
#define HID 256
#define KDIM 100
#define FT_STRIDE 100032      // padded featT row (floats); 16B-divisible
#define TILE_N 64             // nodes per block in node_mm
#define KC 10                 // k-rows per pipeline chunk
#define NCHUNK 10             // KDIM / KC
#define SF_ROW 68             // sF row stride (floats) = 17 x 16B
#define SW_BYTES (KC * HID * 4)      // 10240
#define SF_BYTES (KC * SF_ROW * 4)   // 2720

// ---------------- device scratch ----------------
__device__ __align__(16) float g_agg[N_NODES * IN_CH];      // neighbor sums
__device__ __align__(16) float g_cnt[N_NODES];
__device__ __align__(16) float g_featT[KDIM * FT_STRIDE];   // K-major features (40MB)
__device__ __align__(16) float g_Wt[KDIM * HID];            // K-major weights
__device__ __align__(16) float g_pooled[N_GRAPHS * HID];
__device__ __align__(16) float g_gcnt[N_GRAPHS];

// ---------------- f32x2 / cp.async helpers ----------------
__device__ __forceinline__ unsigned long long pack2(float lo, float hi) {
    unsigned long long r;
    asm("mov.b64 %0, {%1, %2};" : "=l"(r) : "f"(lo), "f"(hi));
    return r;
}
__device__ __forceinline__ void unpack2(unsigned long long v, float& lo, float& hi) {
    asm("mov.b64 {%0, %1}, %2;" : "=f"(lo), "=f"(hi) : "l"(v));
}
__device__ __forceinline__ void ffma2(unsigned long long& d,
                                      unsigned long long a, unsigned long long b) {
    asm("fma.rn.f32x2 %0, %1, %2, %0;" : "+l"(d) : "l"(a), "l"(b));
}
__device__ __forceinline__ uint32_t smem_u32(const void* p) {
    uint32_t a;
    asm("{ .reg .u64 t; cvta.to.shared.u64 t, %1; cvt.u32.u64 %0, t; }"
        : "=r"(a) : "l"(p));
    return a;
}
__device__ __forceinline__ void cp16(uint32_t dst, const void* src) {
    asm volatile("cp.async.ca.shared.global [%0], [%1], 16;"
                 :: "r"(dst), "l"(src) : "memory");
}
#define CP_COMMIT() asm volatile("cp.async.commit_group;" ::: "memory")
#define CP_WAIT1()  asm volatile("cp.async.wait_group 1;" ::: "memory")
#define CP_WAIT0()  asm volatile("cp.async.wait_group 0;" ::: "memory")

// ---------------- kernel 0: zero scratch ----------------
__global__ __launch_bounds__(256) void zero_scratch()
{
    int i = blockIdx.x * blockDim.x + threadIdx.x;
    int stride = gridDim.x * blockDim.x;
    for (; i < N_NODES * IN_CH / 4; i += stride)
        ((float4*)g_agg)[i] = make_float4(0.f, 0.f, 0.f, 0.f);
    for (i = blockIdx.x * blockDim.x + threadIdx.x; i < N_NODES; i += stride)
        g_cnt[i] = 0.f;
    for (i = blockIdx.x * blockDim.x + threadIdx.x; i < N_GRAPHS * HID; i += stride)
        g_pooled[i] = 0.f;
    for (i = blockIdx.x * blockDim.x + threadIdx.x; i < N_GRAPHS; i += stride)
        g_gcnt[i] = 0.f;
}

// ---------------- kernel: build K-major weight matrix ----------------
__global__ __launch_bounds__(256) void build_wt(
    const float* __restrict__ W_l, const float* __restrict__ W_r)
{
    int i = blockIdx.x * 256 + threadIdx.x;
    if (i < KDIM * HID) {
        int k = i / HID, c = i - k * HID;
        g_Wt[i] = (k < IN_CH) ? W_r[c * IN_CH + k] : W_l[c * IN_CH + k - IN_CH];
    }
}

// ---------------- kernel: transpose x -> featT rows [0,50) ----------------
__global__ __launch_bounds__(256) void transpose_x(const float* __restrict__ x)
{
    __shared__ float t[32][33];
    int n0 = blockIdx.x * 32, k0 = blockIdx.y * 32;
    int tx = threadIdx.x, ty = threadIdx.y;
    #pragma unroll
    for (int i = 0; i < 4; i++) {
        int r = ty + 8 * i;
        int k = k0 + tx;
        t[r][tx] = (k < IN_CH) ? x[(n0 + r) * IN_CH + k] : 0.f;
    }
    __syncthreads();
    #pragma unroll
    for (int i = 0; i < 4; i++) {
        int r = ty + 8 * i;
        int k = k0 + r;
        if (k < IN_CH) g_featT[k * FT_STRIDE + n0 + tx] = t[tx][r];
    }
}

// ---------------- kernel: transpose agg*inv -> featT rows [50,100) ---------
__global__ __launch_bounds__(256) void transpose_agg()
{
    __shared__ float t[32][33];
    int n0 = blockIdx.x * 32, k0 = blockIdx.y * 32;
    int tx = threadIdx.x, ty = threadIdx.y;
    #pragma unroll
    for (int i = 0; i < 4; i++) {
        int r = ty + 8 * i;
        int n = n0 + r;
        int k = k0 + tx;
        float inv = 1.0f / fmaxf(g_cnt[n], 1.0f);
        t[r][tx] = (k < IN_CH) ? g_agg[n * IN_CH + k] * inv : 0.f;
    }
    __syncthreads();
    #pragma unroll
    for (int i = 0; i < 4; i++) {
        int r = ty + 8 * i;
        int k = k0 + r;
        if (k < IN_CH) g_featT[(IN_CH + k) * FT_STRIDE + n0 + tx] = t[tx][r];
    }
}

// ---------------- kernel 1: edge scatter-mean (R7-measured-best) -----------
__global__ __launch_bounds__(256) void edge_scatter(
    const int* __restrict__ ei, const float* __restrict__ x)
{
    int warp = (blockIdx.x * blockDim.x + threadIdx.x) >> 5;
    int lane = threadIdx.x & 31;
    int e = warp * 32 + lane;
    int s = ei[e];
    int d = ei[N_EDGES + e];
    const float2* x2 = (const float2*)x;
    #pragma unroll 4
    for (int i = 0; i < 32; i++) {
        int si = __shfl_sync(0xffffffffu, s, i);
        int di = __shfl_sync(0xffffffffu, d, i);
        if (lane < 25) {
            float2 v = x2[si * 25 + lane];
            atomicAdd((float2*)&g_agg[di * IN_CH + lane * 2], v);
        } else if (lane == 25) {
            atomicAdd(&g_cnt[di], 1.0f);
        }
    }
}

// ---------------- kernel 2: nodes per graph (atomic-free) ------------------
__global__ __launch_bounds__(256) void count_nodes(const int* __restrict__ batch)
{
    int i = blockIdx.x * blockDim.x + threadIdx.x;
    if (i >= N_NODES) return;
    int g = batch[i];
    if (i == 0 || batch[i - 1] != g) {
        int j = i + 1;
        while (j < N_NODES && batch[j] == g) j++;
        g_gcnt[g] = (float)(j - i);
    }
}

// ---------------- kernel 3: node GEMM, cp.async double-buffered ------------
// 512 threads, 64 nodes x 256 ch. Thread = 4 ch x 8 nodes (f32x2 node pairs).
// Per chunk: W = contiguous 10KB cp.async, F = 10 rows x 256B cp.async.
__global__ __launch_bounds__(512, 2) void node_mm(
    const int* __restrict__ batch, const float* __restrict__ b_l)
{
    __shared__ float sW[2][KC * HID];       // 2 x 10240 B
    __shared__ float sF[2][KC * SF_ROW];    // 2 x 2720 B
    __shared__ int   sGid[TILE_N];

    int tid = threadIdx.x;
    int n0  = blockIdx.x * TILE_N;

    if (tid < TILE_N) {
        int node = n0 + tid;
        sGid[tid] = (node < N_NODES) ? batch[node] : -1;
    }

    uint32_t swb[2] = {smem_u32(sW[0]), smem_u32(sW[1])};
    uint32_t sfb[2] = {smem_u32(sF[0]), smem_u32(sF[1])};

    // ---- stage chunk kc into buffer b ----
    auto stage = [&](int kc, int b) {
        const char* wsrc = (const char*)g_Wt + kc * SW_BYTES;
        #pragma unroll
        for (int i = tid; i < SW_BYTES / 16; i += 512)
            cp16(swb[b] + i * 16, wsrc + i * 16);
        if (tid < KC * 16) {
            int r = tid >> 4, c16 = tid & 15;
            cp16(sfb[b] + r * (SF_ROW * 4) + c16 * 16,
                 (const char*)(g_featT + (kc * KC + r) * FT_STRIDE + n0) + c16 * 16);
        }
    };

    int tc = tid & 63;   // channel quad
    int tn = tid >> 6;   // node octet

    unsigned long long acc[4][4];
    #pragma unroll
    for (int a = 0; a < 4; a++)
        #pragma unroll
        for (int p = 0; p < 4; p++) acc[a][p] = 0ull;

    stage(0, 0);
    CP_COMMIT();

    for (int c = 0; c < NCHUNK; c++) {
        int b = c & 1;
        if (c + 1 < NCHUNK) {
            stage(c + 1, (c + 1) & 1);
            CP_COMMIT();
            CP_WAIT1();
        } else {
            CP_WAIT0();
        }
        __syncthreads();

        const float4* sW4 = (const float4*)sW[b];          // row = 64 float4
        const ulonglong2* sFu = (const ulonglong2*)sF[b];  // row = 17 u2
        #pragma unroll
        for (int kk = 0; kk < KC; kk++) {
            float4 w = sW4[kk * 64 + tc];
            ulonglong2 fA = sFu[kk * 17 + tn * 2];
            ulonglong2 fB = sFu[kk * 17 + tn * 2 + 1];
            unsigned long long wb2[4];
            wb2[0] = pack2(w.x, w.x);
            wb2[1] = pack2(w.y, w.y);
            wb2[2] = pack2(w.z, w.z);
            wb2[3] = pack2(w.w, w.w);
            unsigned long long fp[4] = {fA.x, fA.y, fB.x, fB.y};
            #pragma unroll
            for (int a = 0; a < 4; a++)
                #pragma unroll
                for (int p = 0; p < 4; p++)
                    ffma2(acc[a][p], wb2[a], fp[p]);
        }
        __syncthreads();
    }

    // epilogue: bias + leakyReLU, run-merged scalar REDs (batch sorted)
    float h[4][8];
    #pragma unroll
    for (int a = 0; a < 4; a++)
        #pragma unroll
        for (int p = 0; p < 4; p++)
            unpack2(acc[a][p], h[a][2 * p], h[a][2 * p + 1]);

    float4 bq = ((const float4*)b_l)[tc];
    float bias[4] = {bq.x, bq.y, bq.z, bq.w};

    float run[4];
    #pragma unroll
    for (int a = 0; a < 4; a++) run[a] = 0.0f;
    int runG = sGid[tn * 8];

    #pragma unroll
    for (int j = 0; j < 8; j++) {
        int g = sGid[tn * 8 + j];
        if (g != runG) {
            if (runG >= 0) {
                #pragma unroll
                for (int a = 0; a < 4; a++)
                    atomicAdd(&g_pooled[runG * HID + tc * 4 + a], run[a]);
            }
            #pragma unroll
            for (int a = 0; a < 4; a++) run[a] = 0.0f;
            runG = g;
        }
        if (g >= 0) {
            #pragma unroll
            for (int a = 0; a < 4; a++) {
                float v = h[a][j] + bias[a];
                v = v > 0.f ? v : 0.01f * v;
                run[a] += v;
            }
        }
    }
    if (runG >= 0) {
        #pragma unroll
        for (int a = 0; a < 4; a++)
            atomicAdd(&g_pooled[runG * HID + tc * 4 + a], run[a]);
    }
}

// ---------------- kernel 4: pooled mean + classifier ----------------
__global__ __launch_bounds__(256) void finalize(
    const float* __restrict__ W_c, const float* __restrict__ b_c,
    float* __restrict__ out)
{
    int g = blockIdx.x;
    int t = threadIdx.x;
    float inv = 1.0f / fmaxf(g_gcnt[g], 1.0f);
    float p = g_pooled[g * HID + t] * inv;
    float s0 = p * W_c[t];
    float s1 = p * W_c[HID + t];
    #pragma unroll
    for (int off = 16; off > 0; off >>= 1) {
        s0 += __shfl_down_sync(0xffffffffu, s0, off);
        s1 += __shfl_down_sync(0xffffffffu, s1, off);
    }
    __shared__ float sh0[8], sh1[8];
    int lane = t & 31, wid = t >> 5;
    if (lane == 0) { sh0[wid] = s0; sh1[wid] = s1; }
    __syncthreads();
    if (t == 0) {
        float t0 = b_c[0], t1 = b_c[1];
        #pragma unroll
        for (int w = 0; w < 8; w++) { t0 += sh0[w]; t1 += sh1[w]; }
        out[g * 2 + 0] = t0;
        out[g * 2 + 1] = t1;
    }
}

// ---------------- launch: kernel launches ONLY ----------------
extern "C" void kernel_launch(void* const* d_in, const int* in_sizes, int n_in,
                              void* d_out, int out_size)
{
    const float* x     = (const float*)d_in[0];
    const int*   ei    = (const int*)d_in[1];    // int32 (JAX x64 disabled)
    const int*   batch = (const int*)d_in[2];    // int32
    const float* W_l   = (const float*)d_in[3];
    const float* b_l   = (const float*)d_in[4];
    const float* W_r   = (const float*)d_in[5];
    const float* W_c   = (const float*)d_in[6];
    const float* b_c   = (const float*)d_in[7];
    float*       out   = (float*)d_out;

    dim3 tgrid(N_NODES / 32, 2), tblk(32, 8);

    zero_scratch<<<592, 256>>>();
    build_wt<<<(KDIM * HID + 255) / 256, 256>>>(W_l, W_r);
    transpose_x<<<tgrid, tblk>>>(x);
    edge_scatter<<<12500, 256>>>(ei, x);
    transpose_agg<<<tgrid, tblk>>>();
    count_nodes<<<(N_NODES + 255) / 256, 256>>>(batch);
    node_mm<<<(N_NODES + TILE_N - 1) / TILE_N, 512>>>(batch, b_l);
    finalize<<<N_GRAPHS, 256>>>(W_c, b_c, out);
}

// round 14
// speedup vs baseline: 1.3817x; 1.0484x over previous
#include <cuda_runtime.h>
#include <cstdint>

#define N_NODES 100000
#define N_EDGES 3200000
#define N_GRAPHS 512
#define IN_CH 50
#define HID 256
#define KDIM 100
#define FT_STRIDE 100032      // padded featT row (floats); 16B-divisible
#define TILE_N 64             // nodes per block in node_mm
#define KC 10                 // k-rows per pipeline chunk
#define NCHUNK 10             // KDIM / KC
#define SF_ROW 68             // sF row stride (floats) = 17 x 16B
#define SW_BYTES (KC * HID * 4)      // 10240
#define NBLK_SCAN 391                // ceil(100000/256)

// ---------------- device scratch ----------------
__device__ __align__(16) float g_featT[KDIM * FT_STRIDE];   // K-major features (40MB)
__device__ __align__(16) float g_Wt[KDIM * HID];            // K-major weights
__device__ __align__(16) float g_pooled[N_GRAPHS * HID];
__device__ __align__(16) float g_gcnt[N_GRAPHS];
__device__ __align__(16) int   g_ptr[N_NODES + 1];          // CSR row pointers
__device__ __align__(16) int   g_cur[N_NODES];              // scatter cursors
__device__ __align__(16) int   g_csr[N_EDGES];              // src sorted by dst
__device__ int g_bsum[NBLK_SCAN];
__device__ int g_bscan[NBLK_SCAN];

// ---------------- f32x2 / cp.async helpers ----------------
__device__ __forceinline__ unsigned long long pack2(float lo, float hi) {
    unsigned long long r;
    asm("mov.b64 %0, {%1, %2};" : "=l"(r) : "f"(lo), "f"(hi));
    return r;
}
__device__ __forceinline__ void unpack2(unsigned long long v, float& lo, float& hi) {
    asm("mov.b64 {%0, %1}, %2;" : "=f"(lo), "=f"(hi) : "l"(v));
}
__device__ __forceinline__ void ffma2(unsigned long long& d,
                                      unsigned long long a, unsigned long long b) {
    asm("fma.rn.f32x2 %0, %1, %2, %0;" : "+l"(d) : "l"(a), "l"(b));
}
__device__ __forceinline__ uint32_t smem_u32(const void* p) {
    uint32_t a;
    asm("{ .reg .u64 t; cvta.to.shared.u64 t, %1; cvt.u32.u64 %0, t; }"
        : "=r"(a) : "l"(p));
    return a;
}
__device__ __forceinline__ void cp16(uint32_t dst, const void* src) {
    asm volatile("cp.async.ca.shared.global [%0], [%1], 16;"
                 :: "r"(dst), "l"(src) : "memory");
}
#define CP_COMMIT() asm volatile("cp.async.commit_group;" ::: "memory")
#define CP_WAIT1()  asm volatile("cp.async.wait_group 1;" ::: "memory")
#define CP_WAIT0()  asm volatile("cp.async.wait_group 0;" ::: "memory")

// ---------------- kernel: zero hist + pooled ----------------
__global__ __launch_bounds__(256) void zero_misc()
{
    int i = blockIdx.x * blockDim.x + threadIdx.x;
    int stride = gridDim.x * blockDim.x;
    for (; i <= N_NODES; i += stride) g_ptr[i] = 0;
    for (i = blockIdx.x * blockDim.x + threadIdx.x; i < N_GRAPHS * HID; i += stride)
        g_pooled[i] = 0.f;
    for (i = blockIdx.x * blockDim.x + threadIdx.x; i < N_GRAPHS; i += stride)
        g_gcnt[i] = 0.f;
}

// ---------------- kernel: build K-major weight matrix ----------------
__global__ __launch_bounds__(256) void build_wt(
    const float* __restrict__ W_l, const float* __restrict__ W_r)
{
    int i = blockIdx.x * 256 + threadIdx.x;
    if (i < KDIM * HID) {
        int k = i / HID, c = i - k * HID;
        g_Wt[i] = (k < IN_CH) ? W_r[c * IN_CH + k] : W_l[c * IN_CH + k - IN_CH];
    }
}

// ---------------- kernel: transpose x -> featT rows [0,50) ----------------
__global__ __launch_bounds__(256) void transpose_x(const float* __restrict__ x)
{
    __shared__ float t[32][33];
    int n0 = blockIdx.x * 32, k0 = blockIdx.y * 32;
    int tx = threadIdx.x, ty = threadIdx.y;
    #pragma unroll
    for (int i = 0; i < 4; i++) {
        int r = ty + 8 * i;
        int k = k0 + tx;
        t[r][tx] = (k < IN_CH) ? x[(n0 + r) * IN_CH + k] : 0.f;
    }
    __syncthreads();
    #pragma unroll
    for (int i = 0; i < 4; i++) {
        int r = ty + 8 * i;
        int k = k0 + r;
        if (k < IN_CH) g_featT[k * FT_STRIDE + n0 + tx] = t[tx][r];
    }
}

// ---------------- CSR build: histogram of dst ----------------
__global__ __launch_bounds__(256) void hist(const int* __restrict__ ei)
{
    int i = blockIdx.x * 256 + threadIdx.x;
    if (i < N_EDGES) atomicAdd(&g_ptr[ei[N_EDGES + i]], 1);
}

// ---------------- CSR build: 3-step exclusive scan of g_ptr[0..N) ---------
__global__ __launch_bounds__(256) void scan_blocks()
{
    __shared__ int s[256];
    int t = threadIdx.x;
    int i = blockIdx.x * 256 + t;
    int v = (i < N_NODES) ? g_ptr[i] : 0;
    s[t] = v;
    __syncthreads();
    for (int o = 1; o < 256; o <<= 1) {
        int u = (t >= o) ? s[t - o] : 0;
        __syncthreads();
        s[t] += u;
        __syncthreads();
    }
    if (i < N_NODES) g_ptr[i] = s[t] - v;        // block-local exclusive
    if (t == 255) g_bsum[blockIdx.x] = s[255];
}
__global__ __launch_bounds__(512) void scan_top()
{
    __shared__ int s[512];
    int t = threadIdx.x;
    int v = (t < NBLK_SCAN) ? g_bsum[t] : 0;
    s[t] = v;
    __syncthreads();
    for (int o = 1; o < 512; o <<= 1) {
        int u = (t >= o) ? s[t - o] : 0;
        __syncthreads();
        s[t] += u;
        __syncthreads();
    }
    if (t < NBLK_SCAN) g_bscan[t] = s[t] - v;    // exclusive
}
__global__ __launch_bounds__(256) void scan_add()
{
    int i = blockIdx.x * 256 + threadIdx.x;
    if (i < N_NODES) {
        int p = g_ptr[i] + g_bscan[blockIdx.x];
        g_ptr[i] = p;
        g_cur[i] = p;
    }
    if (i == 0) g_ptr[N_NODES] = N_EDGES;
}

// ---------------- CSR build: scatter src by dst ----------------
__global__ __launch_bounds__(256) void scatter_csr(const int* __restrict__ ei)
{
    int i = blockIdx.x * 256 + threadIdx.x;
    if (i < N_EDGES) {
        int s = ei[i];
        int d = ei[N_EDGES + i];
        int pos = atomicAdd(&g_cur[d], 1);
        g_csr[pos] = s;
    }
}

// ---------------- aggregate: warp per node, write featT K-major ----------
// Lane owns one channel pair in registers; 32 srcs loaded coalesced then
// shfl-broadcast. Mean folded in; output transposed via smem (atomic-free).
__global__ __launch_bounds__(256) void agg_csr(const float* __restrict__ x)
{
    __shared__ float sT[IN_CH][9];
    int w = threadIdx.x >> 5, lane = threadIdx.x & 31;
    int node = blockIdx.x * 8 + w;       // 12500*8 == N_NODES exactly
    int beg = g_ptr[node], end = g_ptr[node + 1];
    const float2* x2 = (const float2*)x;
    float2 acc = make_float2(0.f, 0.f);
    for (int e = beg; e < end; e += 32) {
        int r = e + lane;
        int sv = (r < end) ? g_csr[r] : 0;
        int m = min(32, end - e);
        for (int i = 0; i < m; i++) {
            int si = __shfl_sync(0xffffffffu, sv, i);
            if (lane < 25) {
                float2 v = x2[si * 25 + lane];
                acc.x += v.x;
                acc.y += v.y;
            }
        }
    }
    float inv = 1.0f / fmaxf((float)(end - beg), 1.0f);
    if (lane < 25) {
        sT[lane * 2][w]     = acc.x * inv;
        sT[lane * 2 + 1][w] = acc.y * inv;
    }
    __syncthreads();
    // FIX (R13 bug): flush loop must grid-stride — IN_CH*8 = 400 > blockDim 256.
    int n0 = blockIdx.x * 8;
    for (int t = threadIdx.x; t < IN_CH * 8; t += 256) {
        int k = t >> 3, j = t & 7;
        g_featT[(IN_CH + k) * FT_STRIDE + n0 + j] = sT[k][j];
    }
}

// ---------------- kernel: nodes per graph (atomic-free) ------------------
__global__ __launch_bounds__(256) void count_nodes(const int* __restrict__ batch)
{
    int i = blockIdx.x * blockDim.x + threadIdx.x;
    if (i >= N_NODES) return;
    int g = batch[i];
    if (i == 0 || batch[i - 1] != g) {
        int j = i + 1;
        while (j < N_NODES && batch[j] == g) j++;
        g_gcnt[g] = (float)(j - i);
    }
}

// ---------------- node GEMM, cp.async double-buffered (R12-best) ----------
__global__ __launch_bounds__(512, 2) void node_mm(
    const int* __restrict__ batch, const float* __restrict__ b_l)
{
    __shared__ float sW[2][KC * HID];
    __shared__ float sF[2][KC * SF_ROW];
    __shared__ int   sGid[TILE_N];

    int tid = threadIdx.x;
    int n0  = blockIdx.x * TILE_N;

    if (tid < TILE_N) {
        int node = n0 + tid;
        sGid[tid] = (node < N_NODES) ? batch[node] : -1;
    }

    uint32_t swb[2] = {smem_u32(sW[0]), smem_u32(sW[1])};
    uint32_t sfb[2] = {smem_u32(sF[0]), smem_u32(sF[1])};

    auto stage = [&](int kc, int b) {
        const char* wsrc = (const char*)g_Wt + kc * SW_BYTES;
        #pragma unroll
        for (int i = tid; i < SW_BYTES / 16; i += 512)
            cp16(swb[b] + i * 16, wsrc + i * 16);
        if (tid < KC * 16) {
            int r = tid >> 4, c16 = tid & 15;
            cp16(sfb[b] + r * (SF_ROW * 4) + c16 * 16,
                 (const char*)(g_featT + (kc * KC + r) * FT_STRIDE + n0) + c16 * 16);
        }
    };

    int tc = tid & 63;
    int tn = tid >> 6;

    unsigned long long acc[4][4];
    #pragma unroll
    for (int a = 0; a < 4; a++)
        #pragma unroll
        for (int p = 0; p < 4; p++) acc[a][p] = 0ull;

    stage(0, 0);
    CP_COMMIT();

    for (int c = 0; c < NCHUNK; c++) {
        int b = c & 1;
        if (c + 1 < NCHUNK) {
            stage(c + 1, (c + 1) & 1);
            CP_COMMIT();
            CP_WAIT1();
        } else {
            CP_WAIT0();
        }
        __syncthreads();

        const float4* sW4 = (const float4*)sW[b];
        const ulonglong2* sFu = (const ulonglong2*)sF[b];
        #pragma unroll
        for (int kk = 0; kk < KC; kk++) {
            float4 w = sW4[kk * 64 + tc];
            ulonglong2 fA = sFu[kk * 17 + tn * 2];
            ulonglong2 fB = sFu[kk * 17 + tn * 2 + 1];
            unsigned long long wb2[4];
            wb2[0] = pack2(w.x, w.x);
            wb2[1] = pack2(w.y, w.y);
            wb2[2] = pack2(w.z, w.z);
            wb2[3] = pack2(w.w, w.w);
            unsigned long long fp[4] = {fA.x, fA.y, fB.x, fB.y};
            #pragma unroll
            for (int a = 0; a < 4; a++)
                #pragma unroll
                for (int p = 0; p < 4; p++)
                    ffma2(acc[a][p], wb2[a], fp[p]);
        }
        __syncthreads();
    }

    float h[4][8];
    #pragma unroll
    for (int a = 0; a < 4; a++)
        #pragma unroll
        for (int p = 0; p < 4; p++)
            unpack2(acc[a][p], h[a][2 * p], h[a][2 * p + 1]);

    float4 bq = ((const float4*)b_l)[tc];
    float bias[4] = {bq.x, bq.y, bq.z, bq.w};

    float run[4];
    #pragma unroll
    for (int a = 0; a < 4; a++) run[a] = 0.0f;
    int runG = sGid[tn * 8];

    #pragma unroll
    for (int j = 0; j < 8; j++) {
        int g = sGid[tn * 8 + j];
        if (g != runG) {
            if (runG >= 0) {
                #pragma unroll
                for (int a = 0; a < 4; a++)
                    atomicAdd(&g_pooled[runG * HID + tc * 4 + a], run[a]);
            }
            #pragma unroll
            for (int a = 0; a < 4; a++) run[a] = 0.0f;
            runG = g;
        }
        if (g >= 0) {
            #pragma unroll
            for (int a = 0; a < 4; a++) {
                float v = h[a][j] + bias[a];
                v = v > 0.f ? v : 0.01f * v;
                run[a] += v;
            }
        }
    }
    if (runG >= 0) {
        #pragma unroll
        for (int a = 0; a < 4; a++)
            atomicAdd(&g_pooled[runG * HID + tc * 4 + a], run[a]);
    }
}

// ---------------- pooled mean + classifier ----------------
__global__ __launch_bounds__(256) void finalize(
    const float* __restrict__ W_c, const float* __restrict__ b_c,
    float* __restrict__ out)
{
    int g = blockIdx.x;
    int t = threadIdx.x;
    float inv = 1.0f / fmaxf(g_gcnt[g], 1.0f);
    float p = g_pooled[g * HID + t] * inv;
    float s0 = p * W_c[t];
    float s1 = p * W_c[HID + t];
    #pragma unroll
    for (int off = 16; off > 0; off >>= 1) {
        s0 += __shfl_down_sync(0xffffffffu, s0, off);
        s1 += __shfl_down_sync(0xffffffffu, s1, off);
    }
    __shared__ float sh0[8], sh1[8];
    int lane = t & 31, wid = t >> 5;
    if (lane == 0) { sh0[wid] = s0; sh1[wid] = s1; }
    __syncthreads();
    if (t == 0) {
        float t0 = b_c[0], t1 = b_c[1];
        #pragma unroll
        for (int w = 0; w < 8; w++) { t0 += sh0[w]; t1 += sh1[w]; }
        out[g * 2 + 0] = t0;
        out[g * 2 + 1] = t1;
    }
}

// ---------------- launch: kernel launches ONLY ----------------
extern "C" void kernel_launch(void* const* d_in, const int* in_sizes, int n_in,
                              void* d_out, int out_size)
{
    const float* x     = (const float*)d_in[0];
    const int*   ei    = (const int*)d_in[1];    // int32 (JAX x64 disabled)
    const int*   batch = (const int*)d_in[2];    // int32
    const float* W_l   = (const float*)d_in[3];
    const float* b_l   = (const float*)d_in[4];
    const float* W_r   = (const float*)d_in[5];
    const float* W_c   = (const float*)d_in[6];
    const float* b_c   = (const float*)d_in[7];
    float*       out   = (float*)d_out;

    dim3 tgrid(N_NODES / 32, 2), tblk(32, 8);
    int eb = (N_EDGES + 255) / 256;

    zero_misc<<<296, 256>>>();
    build_wt<<<(KDIM * HID + 255) / 256, 256>>>(W_l, W_r);
    transpose_x<<<tgrid, tblk>>>(x);
    hist<<<eb, 256>>>(ei);
    scan_blocks<<<NBLK_SCAN, 256>>>();
    scan_top<<<1, 512>>>();
    scan_add<<<NBLK_SCAN, 256>>>();
    scatter_csr<<<eb, 256>>>(ei);
    agg_csr<<<N_NODES / 8, 256>>>(x);
    count_nodes<<<(N_NODES + 255) / 256, 256>>>(batch);
    node_mm<<<(N_NODES + TILE_N - 1) / TILE_N, 512>>>(batch, b_l);
    finalize<<<N_GRAPHS, 256>>>(W_c, b_c, out);
}